// round 12
// baseline (speedup 1.0000x reference)
#include <cuda_runtime.h>
#include <math.h>

// ---------------------------------------------------------------------------
// SparseInst post-processing pipeline, fixed shapes:
//   pred_logits     [1,1,128,128]   -> 16384 fp32
//   embedding_masks [1,128,128,128] -> [128][16384]
//   encode_feat     [1,128,512,512] -> [128][262144]
//   K = 400
// Outputs (flattened float): final_scores[400], pred_masks_s[400*262144],
//                            keep_final[400], center_index[400]
//
// Numerical contract (established over rounds 4-9):
//  * matmuls: exact fp32, ascending-k serial FMA chain (TF32 falsified: R6
//    error 4.5x worse; R5 exact-fp32 error small).
//  * seg row-sum order: irrelevant at current error level (fp64-exact and
//    XLA-tree orders gave bit-identical results) -> keep XLA-GPU tree.
//  * sigmoid: XLA logistic_expander form 0.5 + 0.5*tanh(0.5x) with XLA
//    FastTanh f32 rational (clamp +-7.90531110763549805, |x|<4e-4 -> x).
//    This round's single change: use it for scores AND all mask pixels.
// ---------------------------------------------------------------------------

#define KTOP   400
#define DIM    128
#define HW     16384
#define NPIX   262144
#define WORDS  8192          // NPIX/32
#define KPAD   416           // 13*32
#define NCHUNK 13
#define NBLK   1024          // gemm blocks
#define OUT_MASK 400
#define OUT_KEEP 104858000   // 400 + 400*262144
#define OUT_IDX  104858400

// ------------------------------ scratch ------------------------------------
__device__ float         g_scores[KTOP];
__device__ int           g_index[KTOP];
__device__ int           g_valid[KTOP];
__device__ float         g_feat[KTOP * DIM];
__device__ float         g_fn[KTOP * DIM];
__device__ float         g_sim[KTOP * KTOP];
__device__ int           g_first[KTOP];
__device__ int           g_keep[KTOP];
__device__ float         g_metanT[DIM * KPAD];         // [d][row]
__device__ float         g_pred[(size_t)KTOP * NPIX];  // unsorted masks (419MB)
__device__ unsigned int  g_bits[KTOP * WORDS];         // segf bitmask
__device__ float         g_segsum[KTOP];
__device__ float         g_summask[KTOP];
__device__ float         g_cate[KTOP];
__device__ float         g_cate_s[KTOP];
__device__ int           g_keeps[KTOP];
__device__ float         g_summask_s[KTOP];
__device__ int           g_order[KTOP];
__device__ int           g_inter[KTOP * KTOP];
__device__ float         g_iou[KTOP * KTOP];
__device__ float         g_comp[KTOP];

// ------------------------------ helpers ------------------------------------
__device__ __forceinline__ unsigned ford(float f) {
    unsigned u = __float_as_uint(f);
    return (u & 0x80000000u) ? ~u : (u | 0x80000000u);
}

// XLA FastTanh (f32): |x|<0.0004 -> x; clamp +-7.90531110763549805;
// odd rational with the exact XLA alpha/beta coefficients, FMA chains.
__device__ __forceinline__ float xla_tanh(float x) {
    if (fabsf(x) < 0.0004f) return x;
    float xc = fminf(fmaxf(x, -7.90531110763549805f), 7.90531110763549805f);
    float x2 = __fmul_rn(xc, xc);
    float p = __fmaf_rn(x2, -2.76076847742355e-16f, 2.00018790482477e-13f);
    p = __fmaf_rn(x2, p, -8.60467152213735e-11f);
    p = __fmaf_rn(x2, p,  5.12229709037114e-08f);
    p = __fmaf_rn(x2, p,  1.48572235717979e-05f);
    p = __fmaf_rn(x2, p,  6.37261928875436e-04f);
    p = __fmaf_rn(x2, p,  4.89352455891786e-03f);
    p = __fmul_rn(p, xc);
    float q = __fmaf_rn(x2, 1.19825839466702e-06f, 1.18534705686654e-04f);
    q = __fmaf_rn(x2, q, 2.26843463243900e-03f);
    q = __fmaf_rn(x2, q, 4.89352518554385e-03f);
    return __fdiv_rn(p, q);
}

// XLA logistic expansion: 0.5 + 0.5*tanh(0.5*x), ops rounded individually
__device__ __forceinline__ float xla_sigmoid(float x) {
    float t = xla_tanh(__fmul_rn(0.5f, x));
    return __fadd_rn(0.5f, __fmul_rn(0.5f, t));
}

__device__ __forceinline__ void ffma2(unsigned long long &acc,
                                      unsigned long long a,
                                      unsigned long long b) {
    asm("fma.rn.f32x2 %0, %1, %2, %0;" : "+l"(acc) : "l"(a), "l"(b));
}

// ------------------------------ K0: init -----------------------------------
__global__ void k_init() {
    int i = blockIdx.x * 256 + threadIdx.x;
    if (i < KTOP * KTOP) g_inter[i] = 0;
}

// ------------------ K1: sigmoid + exact stable top-400 ----------------------
__global__ void k_topk(const float* __restrict__ logits) {
    __shared__ unsigned long long cand[4096];   // aliased as hist in phase 1
    __shared__ int s_cnt, s_bin;
    int* hist = (int*)cand;
    int tid = threadIdx.x;
    for (int i = tid; i < 4096; i += 1024) hist[i] = 0;
    if (tid == 0) s_cnt = 0;
    __syncthreads();
    for (int i = tid; i < HW; i += 1024) {
        float p = xla_sigmoid(logits[i]);
        unsigned d = ~ford(p);                 // ascending d == descending p
        atomicAdd(&hist[d >> 19], 1);          // d < 2^31 -> bin < 4096
    }
    __syncthreads();
    if (tid == 0) {
        int c = 0, b = 0;
        for (; b < 4096; b++) { c += hist[b]; if (c >= KTOP) break; }
        s_bin = b;
    }
    __syncthreads();
    int bt = s_bin;
    for (int i = tid; i < 4096; i += 1024) cand[i] = ~0ull;  // clear (aliases hist)
    __syncthreads();
    for (int i = tid; i < HW; i += 1024) {
        float p = xla_sigmoid(logits[i]);
        unsigned d = ~ford(p);
        if ((int)(d >> 19) <= bt) {
            int pos = atomicAdd(&s_cnt, 1);
            if (pos < 4096)
                cand[pos] = (((unsigned long long)d) << 32) | (unsigned)i;
        }
    }
    __syncthreads();
    // bitonic sort ascending: (desc value, asc index) == lax.top_k order
    for (int k = 2; k <= 4096; k <<= 1)
        for (int j = k >> 1; j > 0; j >>= 1) {
            for (int i = tid; i < 4096; i += 1024) {
                int ixj = i ^ j;
                if (ixj > i) {
                    unsigned long long a = cand[i], b2 = cand[ixj];
                    bool up = ((i & k) == 0);
                    if ((a > b2) == up) { cand[i] = b2; cand[ixj] = a; }
                }
            }
            __syncthreads();
        }
    if (tid < KTOP) {
        unsigned long long kk = cand[tid];
        unsigned fo = ~((unsigned)(kk >> 32));
        float p = __uint_as_float(fo & 0x7FFFFFFFu);   // p in [0,1)
        g_scores[tid] = p;
        g_index[tid]  = (int)(kk & 0xFFFFFFFFu);
        g_valid[tid]  = (p > 0.75f) ? 1 : 0;
    }
}

// -------------------- K2: gather feat + normalize ---------------------------
// XLA-GPU small-row reduce: strided ascending serial (d,d+32,d+64,d+96),
// then shfl tree.
__global__ void k_feat(const float* __restrict__ em) {
    int i = blockIdx.x, d = threadIdx.x;
    __shared__ float sq[DIM];
    __shared__ float snrm;
    int idx = g_index[i];
    float f = em[d * HW + idx];
    sq[d] = f * f;
    __syncthreads();
    if (d < 32) {
        float a = __fadd_rn(__fadd_rn(__fadd_rn(sq[d], sq[d + 32]),
                                      sq[d + 64]), sq[d + 96]);
        #pragma unroll
        for (int o = 16; o; o >>= 1)
            a = __fadd_rn(a, __shfl_down_sync(0xffffffffu, a, o));
        if (d == 0) snrm = __fsqrt_rn(a);
    }
    __syncthreads();
    float nrm = fmaxf(snrm, 1e-8f);
    g_feat[i * DIM + d] = f;
    g_fn[i * DIM + d]   = __fdiv_rn(f, nrm);
}

// -------------------- K3: sim = fn @ fn.T -----------------------------------
// (0.85 threshold margins are many sigma wide; order-insensitive)
__global__ void k_sim() {
    int i = blockIdx.x, t = threadIdx.x;
    __shared__ float fi[DIM];
    fi[t] = g_fn[i * DIM + t];
    __syncthreads();
    for (int jj = t; jj < KTOP; jj += DIM) {
        const float* fj = &g_fn[jj * DIM];
        float s = 0.f;
        #pragma unroll 8
        for (int d = 0; d < DIM; d++) s = __fmaf_rn(fi[d], fj[d], s);
        g_sim[i * KTOP + jj] = s;
    }
}

// -------------------- K4: first-label column + keep -------------------------
__global__ void k_firstkeep() {
    int j = threadIdx.x;
    if (j >= KTOP) return;
    int first = -1;
    if (g_valid[j]) {
        for (int i = 0; i <= j; i++) {
            if (g_valid[i] && g_sim[i * KTOP + j] >= 0.85f) { first = i; break; }
        }
    }
    g_first[j] = first;
    g_keep[j]  = (g_valid[j] && first == j) ? 1 : 0;
}

// -------------------- K5: meta fusion + normalize -> metanT -----------------
__global__ void k_meta() {
    int i = blockIdx.x, d = threadIdx.x;
    __shared__ float sq[DIM];
    __shared__ float snrm;
    float meta = 0.f;
    if (i < KTOP) {
        float s = 0.f; int cnt = 0;
        for (int j = 0; j < KTOP; j++) {          // ascending j == dot order
            if (g_first[j] == i) { s = __fadd_rn(s, g_feat[j * DIM + d]); cnt++; }
        }
        meta = g_keep[i] ? __fdiv_rn(s, fmaxf((float)cnt, 1.f)) : 0.f;
    }
    sq[d] = meta * meta;
    __syncthreads();
    if (d < 32) {
        float a = __fadd_rn(__fadd_rn(__fadd_rn(sq[d], sq[d + 32]),
                                      sq[d + 64]), sq[d + 96]);
        #pragma unroll
        for (int o = 16; o; o >>= 1)
            a = __fadd_rn(a, __shfl_down_sync(0xffffffffu, a, o));
        if (d == 0) snrm = __fsqrt_rn(a);
    }
    __syncthreads();
    float nrm = fmaxf(snrm, 1e-8f);
    g_metanT[d * KPAD + i] = (i < KTOP) ? __fdiv_rn(meta, nrm) : 0.f;
}

// -------------------- K6: big GEMM + fused epilogue -------------------------
__device__ __forceinline__ void emit_row(int row, float xa, float xb,
                                         int pxb, int tid, int lane, int warp,
                                         int kp) {
    float m  = kp ? 1.f : 0.f;
    float v0 = __fmul_rn(m, xla_sigmoid(xa));   // XLA tanh-form everywhere
    float v1 = __fmul_rn(m, xla_sigmoid(xb));
    size_t base = (size_t)row * NPIX + pxb;
    g_pred[base + tid]       = v0;
    g_pred[base + 128 + tid] = v1;
    unsigned mm0 = __ballot_sync(0xffffffffu, v0 > 0.45f);
    unsigned mm1 = __ballot_sync(0xffffffffu, v1 > 0.45f);
    if (lane == 0) {
        g_bits[row * WORDS + (pxb >> 5) + warp]     = mm0;
        g_bits[row * WORDS + (pxb >> 5) + 4 + warp] = mm1;
    }
}

extern __shared__ float smem_dyn[];

__global__ void __launch_bounds__(128) k_gemm(const float* __restrict__ E) {
    float* sE = smem_dyn;              // 128 x 256 = 131072 B
    float* sA = smem_dyn + 128 * 256;  // 128 x  32 =  16384 B
    __shared__ int skeep[KTOP];
    int tid  = threadIdx.x;
    int pxb  = blockIdx.x * 256;
    int lane = tid & 31, warp = tid >> 5;

    for (int i = tid; i < KTOP; i += 128) skeep[i] = g_keep[i];

    // stage E tile once (E read from HBM exactly once across the grid)
    const float4* E4  = (const float4*)E;
    float4*       sE4 = (float4*)sE;
    int pxb4 = pxb >> 2;
    for (int i = tid; i < 128 * 64; i += 128) {
        int d = i >> 6, c = i & 63;
        sE4[d * 64 + c] = E4[d * (NPIX / 4) + pxb4 + c];
    }

    for (int chunk = 0; chunk < NCHUNK; ++chunk) {
        __syncthreads();
        for (int i = tid; i < 128 * 32; i += 128) {
            int d = i >> 5, r = i & 31;
            sA[d * 32 + r] = g_metanT[d * KPAD + chunk * 32 + r];
        }
        __syncthreads();

        unsigned long long a0[16], a1[16];
        #pragma unroll
        for (int r = 0; r < 16; r++) { a0[r] = 0ull; a1[r] = 0ull; }

        // ascending-k serial FMA chain per output: bit-identical to
        // cuBLAS-fp32 accumulation for K=128 (no split-K)
        #pragma unroll 4
        for (int d = 0; d < 128; d++) {
            float e0 = sE[d * 256 + tid];
            float e1 = sE[d * 256 + 128 + tid];
            unsigned eu0 = __float_as_uint(e0), eu1 = __float_as_uint(e1);
            unsigned long long e00, e11;
            asm("mov.b64 %0, {%1, %1};" : "=l"(e00) : "r"(eu0));
            asm("mov.b64 %0, {%1, %1};" : "=l"(e11) : "r"(eu1));
            const unsigned long long* ap =
                (const unsigned long long*)&sA[d * 32];
            #pragma unroll
            for (int r = 0; r < 16; r++) {
                unsigned long long av = ap[r];   // rows (2r,2r+1), broadcast
                ffma2(a0[r], av, e00);
                ffma2(a1[r], av, e11);
            }
        }

        int cb = chunk * 32;
        #pragma unroll
        for (int r = 0; r < 16; r++) {
            unsigned lo0, hi0, lo1, hi1;
            asm("mov.b64 {%0, %1}, %2;" : "=r"(lo0), "=r"(hi0) : "l"(a0[r]));
            asm("mov.b64 {%0, %1}, %2;" : "=r"(lo1), "=r"(hi1) : "l"(a1[r]));
            int row0 = cb + 2 * r;
            if (row0 < KTOP)
                emit_row(row0, __uint_as_float(lo0), __uint_as_float(lo1),
                         pxb, tid, lane, warp, skeep[row0]);
            int row1 = row0 + 1;
            if (row1 < KTOP)
                emit_row(row1, __uint_as_float(hi0), __uint_as_float(hi1),
                         pxb, tid, lane, warp, skeep[row1]);
        }
    }
}

// ---------------- K6b: XLA-GPU-order fp32 seg-sum emulation -----------------
// One block per row. 1024 threads; thread t accumulates float2 elements
// (2*(t+1024m), 2*(t+1024m)+1), m ascending, two fp32 lane accumulators;
// lane-pair add; warp shfl.down tree; smem warp partials; warp-0 tree.
// Masked adds of +0.0 are fp32 identity. Count is an exact integer.
__global__ void __launch_bounds__(1024) k_segsum() {   // <<<KTOP, 1024>>>
    __shared__ float wp[32];
    __shared__ int   wc[32];
    int row = blockIdx.x, t = threadIdx.x;
    int lane = t & 31, warp = t >> 5;
    const float2* p = (const float2*)&g_pred[(size_t)row * NPIX];
    float a0 = 0.f, a1 = 0.f;
    int c = 0;
    #pragma unroll 4
    for (int m2 = 0; m2 < NPIX / 2048; m2++) {   // 128 iters
        float2 v = p[t + 1024 * m2];
        if (v.x > 0.45f) { a0 = __fadd_rn(a0, v.x); c++; }
        if (v.y > 0.45f) { a1 = __fadd_rn(a1, v.y); c++; }
    }
    float a = __fadd_rn(a0, a1);
    #pragma unroll
    for (int o = 16; o; o >>= 1) {
        a = __fadd_rn(a, __shfl_down_sync(0xffffffffu, a, o));
        c += __shfl_down_sync(0xffffffffu, c, o);
    }
    if (lane == 0) { wp[warp] = a; wc[warp] = c; }
    __syncthreads();
    if (warp == 0) {
        float b = wp[lane];
        int   d = wc[lane];
        #pragma unroll
        for (int o = 16; o; o >>= 1) {
            b = __fadd_rn(b, __shfl_down_sync(0xffffffffu, b, o));
            d += __shfl_down_sync(0xffffffffu, d, o);
        }
        if (lane == 0) { g_segsum[row] = b; g_summask[row] = (float)d; }
    }
}

// -------------------- K7: cate scores + stable argsort ----------------------
__global__ void k_sort() {
    __shared__ unsigned long long key[512];
    int t = threadIdx.x;
    if (t < KTOP) {
        float seg  = __fdiv_rn(g_segsum[t], fmaxf(g_summask[t], 1.f));
        float cate = __fmul_rn(__fmul_rn(g_scores[t], seg),
                               g_keep[t] ? 1.f : 0.f);
        g_cate[t] = cate;
        float v = (cate > 0.f) ? -cate : 0.f;   // canonicalize zeros
        key[t] = (((unsigned long long)ford(v)) << 32) | (unsigned)t;
    } else key[t] = ~0ull;
    __syncthreads();
    for (int k = 2; k <= 512; k <<= 1)
        for (int j = k >> 1; j > 0; j >>= 1) {
            int i = t, ixj = i ^ j;
            if (ixj > i) {
                unsigned long long a = key[i], b = key[ixj];
                bool up = ((i & k) == 0);
                if ((a > b) == up) { key[i] = b; key[ixj] = a; }
            }
            __syncthreads();
        }
    if (t < KTOP) {
        int o = (int)(key[t] & 0xFFFFFFFFu);
        g_order[t]     = o;
        g_cate_s[t]    = g_cate[o];
        g_keeps[t]     = g_keep[o];
        g_summask_s[t] = g_summask[o];
    }
}

// -------------------- K8: bit-packed intersection SYRK ----------------------
// (0/1 operands, sums < 2^24: exact under any reference precision)
__global__ void k_inter() {
    __shared__ unsigned sAb[32 * 33];
    __shared__ unsigned sBb[32 * 33];
    int t = threadIdx.x;                 // 256
    int b = blockIdx.x;                  // 0..90 triangular tile
    int ti = 0, rem = b;
    while (rem >= 13 - ti) { rem -= 13 - ti; ti++; }
    int tj = ti + rem;
    int wbase0 = blockIdx.y * 1024;
    int i0 = t >> 5;
    int jj = t & 31;
    int cnt[4] = {0, 0, 0, 0};
    for (int cc = 0; cc < 32; cc++) {
        int wb = wbase0 + cc * 32;
        for (int x = t; x < 1024; x += 256) {
            int r = x >> 5, c = x & 31;
            int ra = ti * 32 + r, rb = tj * 32 + r;
            sAb[c * 33 + r] = (ra < KTOP) ? g_bits[ra * WORDS + wb + c] : 0u;
            sBb[c * 33 + r] = (rb < KTOP) ? g_bits[rb * WORDS + wb + c] : 0u;
        }
        __syncthreads();
        #pragma unroll 4
        for (int w = 0; w < 32; w++) {
            unsigned bv = sBb[w * 33 + jj];
            #pragma unroll
            for (int k2 = 0; k2 < 4; k2++) {
                unsigned av = sAb[w * 33 + i0 + 8 * k2];
                cnt[k2] += __popc(av & bv);
            }
        }
        __syncthreads();
    }
    #pragma unroll
    for (int k2 = 0; k2 < 4; k2++) {
        int ii = ti * 32 + i0 + 8 * k2;
        int j2 = tj * 32 + jj;
        if (ii < KTOP && j2 < KTOP) {
            atomicAdd(&g_inter[ii * KTOP + j2], cnt[k2]);
            if (ti != tj) atomicAdd(&g_inter[j2 * KTOP + ii], cnt[k2]);
        }
    }
}

// -------------------- K9: sorted IoU + column max ---------------------------
__global__ void k_iou1() {
    __shared__ float sms[KTOP];
    __shared__ int   ords[KTOP];
    int t = threadIdx.x;                  // 512
    if (t < KTOP) { sms[t] = g_summask_s[t]; ords[t] = g_order[t]; }
    __syncthreads();
    if (t >= KTOP) return;
    int j = t, b2 = ords[j];
    float smj = sms[j], comp = 0.f;
    for (int i = 0; i < j; i++) {
        float it  = (float)g_inter[ords[i] * KTOP + b2];
        float den = __fadd_rn(__fadd_rn(sms[i], smj), -it);
        float iou = (den > 0.f) ? __fdiv_rn(it, fmaxf(den, 1.f)) : 0.f;
        g_iou[i * KTOP + j] = iou;
        comp = fmaxf(comp, iou);
    }
    g_comp[j] = comp;
}

// -------------------- K10: matrix-NMS decay + small outputs -----------------
__global__ void k_nms2(float* __restrict__ out) {
    __shared__ float den[KTOP];
    int t = threadIdx.x;                  // 512
    if (t < KTOP) {
        float c  = g_comp[t];
        float c2 = __fmul_rn(c, c);       // exp(-SIGMA * x**2) association
        den[t] = expf(__fmul_rn(-2.f, c2));
    }
    __syncthreads();
    if (t >= KTOP) return;
    int j = t;
    float dmin = 3.4e38f;
    for (int i = 0; i < KTOP; i++) {
        float d  = (i < j) ? g_iou[i * KTOP + j] : 0.f;
        float d2 = __fmul_rn(d, d);
        float term = __fdiv_rn(expf(__fmul_rn(-2.f, d2)), den[i]);
        dmin = fminf(dmin, term);
    }
    float fs = __fmul_rn(g_cate_s[j], dmin);
    out[j]            = fs;
    out[OUT_KEEP + j] = (fs >= 0.8f && g_keeps[j]) ? 1.f : 0.f;
    out[OUT_IDX + j]  = (float)g_index[g_order[j]];
}

// -------------------- K11: permuted float4 mask copy ------------------------
__global__ void k_copy(float* __restrict__ out) {
    int i   = blockIdx.y;
    int src = g_order[i];
    int f4  = blockIdx.x * 256 + threadIdx.x;
    const float4* s = (const float4*)&g_pred[(size_t)src * NPIX];
    float4* d       = (float4*)(out + OUT_MASK + (size_t)i * NPIX);
    d[f4] = s[f4];
}

// ---------------------------------------------------------------------------
extern "C" void kernel_launch(void* const* d_in, const int* in_sizes, int n_in,
                              void* d_out, int out_size) {
    const float* logits = (const float*)d_in[0];
    const float* em     = (const float*)d_in[1];
    const float* E      = (const float*)d_in[2];
    float* out = (float*)d_out;

    cudaFuncSetAttribute(k_gemm, cudaFuncAttributeMaxDynamicSharedMemorySize,
                         147456);

    k_init<<<625, 256>>>();
    k_topk<<<1, 1024>>>(logits);
    k_feat<<<KTOP, DIM>>>(em);
    k_sim<<<KTOP, DIM>>>();
    k_firstkeep<<<1, 512>>>();
    k_meta<<<KPAD, DIM>>>();
    k_gemm<<<NBLK, 128, 147456>>>(E);
    k_segsum<<<KTOP, 1024>>>();
    k_sort<<<1, 512>>>();
    k_inter<<<dim3(91, 8), 256>>>();
    k_iou1<<<1, 512>>>();
    k_nms2<<<1, 512>>>(out);
    k_copy<<<dim3(256, 400), 256>>>(out);
}

// round 15
// speedup vs baseline: 1.4314x; 1.4314x over previous
#include <cuda_runtime.h>
#include <math.h>

// ---------------------------------------------------------------------------
// SparseInst post-processing pipeline, fixed shapes:
//   pred_logits     [1,1,128,128]   -> 16384 fp32
//   embedding_masks [1,128,128,128] -> [128][16384]
//   encode_feat     [1,128,512,512] -> [128][262144]
//   K = 400
// Outputs: final_scores[400], pred_masks_s[400*262144], keep_final[400],
//          center_index[400]
//
// Numerical contract (validated PASS in round 11):
//  * matmuls: exact fp32, ascending-k serial FMA chain per output.
//  * sigmoid: XLA logistic_expander 0.5 + 0.5*tanh(0.5x), XLA FastTanh f32.
//  * seg row-sum: XLA-GPU tree order (k_segsum unchanged).
// This round only restructures k_gemm for occupancy (bit-identical math)
// and vectorizes k_sim (bit-identical chain, upper triangle only).
// ---------------------------------------------------------------------------

#define KTOP   400
#define DIM    128
#define HW     16384
#define NPIX   262144
#define WORDS  8192          // NPIX/32
#define KPAD   416           // 13*32
#define NCHUNK 13
#define NBLK   1024          // gemm blocks
#define OUT_MASK 400
#define OUT_KEEP 104858000   // 400 + 400*262144
#define OUT_IDX  104858400

// ------------------------------ scratch ------------------------------------
__device__ float         g_scores[KTOP];
__device__ int           g_index[KTOP];
__device__ int           g_valid[KTOP];
__device__ float         g_feat[KTOP * DIM];
__device__ float         g_fn[KTOP * DIM];
__device__ float         g_sim[KTOP * KTOP];
__device__ int           g_first[KTOP];
__device__ int           g_keep[KTOP];
__device__ float         g_metanT[DIM * KPAD];         // [d][row]
__device__ float         g_pred[(size_t)KTOP * NPIX];  // unsorted masks (419MB)
__device__ unsigned int  g_bits[KTOP * WORDS];         // segf bitmask
__device__ float         g_segsum[KTOP];
__device__ float         g_summask[KTOP];
__device__ float         g_cate[KTOP];
__device__ float         g_cate_s[KTOP];
__device__ int           g_keeps[KTOP];
__device__ float         g_summask_s[KTOP];
__device__ int           g_order[KTOP];
__device__ int           g_inter[KTOP * KTOP];
__device__ float         g_iou[KTOP * KTOP];
__device__ float         g_comp[KTOP];

// ------------------------------ helpers ------------------------------------
__device__ __forceinline__ unsigned ford(float f) {
    unsigned u = __float_as_uint(f);
    return (u & 0x80000000u) ? ~u : (u | 0x80000000u);
}

// XLA FastTanh (f32): |x|<0.0004 -> x; clamp +-7.90531110763549805;
// odd rational with the exact XLA alpha/beta coefficients, FMA chains.
__device__ __forceinline__ float xla_tanh(float x) {
    if (fabsf(x) < 0.0004f) return x;
    float xc = fminf(fmaxf(x, -7.90531110763549805f), 7.90531110763549805f);
    float x2 = __fmul_rn(xc, xc);
    float p = __fmaf_rn(x2, -2.76076847742355e-16f, 2.00018790482477e-13f);
    p = __fmaf_rn(x2, p, -8.60467152213735e-11f);
    p = __fmaf_rn(x2, p,  5.12229709037114e-08f);
    p = __fmaf_rn(x2, p,  1.48572235717979e-05f);
    p = __fmaf_rn(x2, p,  6.37261928875436e-04f);
    p = __fmaf_rn(x2, p,  4.89352455891786e-03f);
    p = __fmul_rn(p, xc);
    float q = __fmaf_rn(x2, 1.19825839466702e-06f, 1.18534705686654e-04f);
    q = __fmaf_rn(x2, q, 2.26843463243900e-03f);
    q = __fmaf_rn(x2, q, 4.89352518554385e-03f);
    return __fdiv_rn(p, q);
}

// XLA logistic expansion: 0.5 + 0.5*tanh(0.5*x), ops rounded individually
__device__ __forceinline__ float xla_sigmoid(float x) {
    float t = xla_tanh(__fmul_rn(0.5f, x));
    return __fadd_rn(0.5f, __fmul_rn(0.5f, t));
}

__device__ __forceinline__ void ffma2(unsigned long long &acc,
                                      unsigned long long a,
                                      unsigned long long b) {
    asm("fma.rn.f32x2 %0, %1, %2, %0;" : "+l"(acc) : "l"(a), "l"(b));
}

// ------------------------------ K0: init -----------------------------------
__global__ void k_init() {
    int i = blockIdx.x * 256 + threadIdx.x;
    if (i < KTOP * KTOP) g_inter[i] = 0;
}

// ------------------ K1: sigmoid + exact stable top-400 ----------------------
__global__ void k_topk(const float* __restrict__ logits) {
    __shared__ unsigned long long cand[4096];   // aliased as hist in phase 1
    __shared__ int s_cnt, s_bin;
    int* hist = (int*)cand;
    int tid = threadIdx.x;
    for (int i = tid; i < 4096; i += 1024) hist[i] = 0;
    if (tid == 0) s_cnt = 0;
    __syncthreads();
    for (int i = tid; i < HW; i += 1024) {
        float p = xla_sigmoid(logits[i]);
        unsigned d = ~ford(p);                 // ascending d == descending p
        atomicAdd(&hist[d >> 19], 1);          // d < 2^31 -> bin < 4096
    }
    __syncthreads();
    if (tid == 0) {
        int c = 0, b = 0;
        for (; b < 4096; b++) { c += hist[b]; if (c >= KTOP) break; }
        s_bin = b;
    }
    __syncthreads();
    int bt = s_bin;
    for (int i = tid; i < 4096; i += 1024) cand[i] = ~0ull;  // clear (aliases hist)
    __syncthreads();
    for (int i = tid; i < HW; i += 1024) {
        float p = xla_sigmoid(logits[i]);
        unsigned d = ~ford(p);
        if ((int)(d >> 19) <= bt) {
            int pos = atomicAdd(&s_cnt, 1);
            if (pos < 4096)
                cand[pos] = (((unsigned long long)d) << 32) | (unsigned)i;
        }
    }
    __syncthreads();
    // bitonic sort ascending: (desc value, asc index) == lax.top_k order
    for (int k = 2; k <= 4096; k <<= 1)
        for (int j = k >> 1; j > 0; j >>= 1) {
            for (int i = tid; i < 4096; i += 1024) {
                int ixj = i ^ j;
                if (ixj > i) {
                    unsigned long long a = cand[i], b2 = cand[ixj];
                    bool up = ((i & k) == 0);
                    if ((a > b2) == up) { cand[i] = b2; cand[ixj] = a; }
                }
            }
            __syncthreads();
        }
    if (tid < KTOP) {
        unsigned long long kk = cand[tid];
        unsigned fo = ~((unsigned)(kk >> 32));
        float p = __uint_as_float(fo & 0x7FFFFFFFu);   // p in [0,1)
        g_scores[tid] = p;
        g_index[tid]  = (int)(kk & 0xFFFFFFFFu);
        g_valid[tid]  = (p > 0.75f) ? 1 : 0;
    }
}

// -------------------- K2: gather feat + normalize ---------------------------
__global__ void k_feat(const float* __restrict__ em) {
    int i = blockIdx.x, d = threadIdx.x;
    __shared__ float sq[DIM];
    __shared__ float snrm;
    int idx = g_index[i];
    float f = em[d * HW + idx];
    sq[d] = f * f;
    __syncthreads();
    if (d < 32) {
        float a = __fadd_rn(__fadd_rn(__fadd_rn(sq[d], sq[d + 32]),
                                      sq[d + 64]), sq[d + 96]);
        #pragma unroll
        for (int o = 16; o; o >>= 1)
            a = __fadd_rn(a, __shfl_down_sync(0xffffffffu, a, o));
        if (d == 0) snrm = __fsqrt_rn(a);
    }
    __syncthreads();
    float nrm = fmaxf(snrm, 1e-8f);
    g_feat[i * DIM + d] = f;
    g_fn[i * DIM + d]   = __fdiv_rn(f, nrm);
}

// -------------------- K3: sim = fn @ fn.T (upper triangle) ------------------
// float4 loads; chain order per output identical to scalar ascending-d FMA.
__global__ void k_sim() {
    int i = blockIdx.x, t = threadIdx.x;
    __shared__ float fi[DIM];
    fi[t] = g_fn[i * DIM + t];
    __syncthreads();
    for (int jj = i + t; jj < KTOP; jj += DIM) {   // only j >= i is ever read
        const float4* fj = (const float4*)&g_fn[jj * DIM];
        float s = 0.f;
        #pragma unroll
        for (int d4 = 0; d4 < 32; d4++) {
            float4 v = fj[d4];
            int k = d4 * 4;
            s = __fmaf_rn(fi[k],     v.x, s);
            s = __fmaf_rn(fi[k + 1], v.y, s);
            s = __fmaf_rn(fi[k + 2], v.z, s);
            s = __fmaf_rn(fi[k + 3], v.w, s);
        }
        g_sim[i * KTOP + jj] = s;
    }
}

// -------------------- K4: first-label column + keep -------------------------
__global__ void k_firstkeep() {
    int j = threadIdx.x;
    if (j >= KTOP) return;
    int first = -1;
    if (g_valid[j]) {
        for (int i = 0; i <= j; i++) {
            if (g_valid[i] && g_sim[i * KTOP + j] >= 0.85f) { first = i; break; }
        }
    }
    g_first[j] = first;
    g_keep[j]  = (g_valid[j] && first == j) ? 1 : 0;
}

// -------------------- K5: meta fusion + normalize -> metanT -----------------
__global__ void k_meta() {
    int i = blockIdx.x, d = threadIdx.x;
    __shared__ float sq[DIM];
    __shared__ float snrm;
    float meta = 0.f;
    if (i < KTOP) {
        float s = 0.f; int cnt = 0;
        for (int j = 0; j < KTOP; j++) {          // ascending j == dot order
            if (g_first[j] == i) { s = __fadd_rn(s, g_feat[j * DIM + d]); cnt++; }
        }
        meta = g_keep[i] ? __fdiv_rn(s, fmaxf((float)cnt, 1.f)) : 0.f;
    }
    sq[d] = meta * meta;
    __syncthreads();
    if (d < 32) {
        float a = __fadd_rn(__fadd_rn(__fadd_rn(sq[d], sq[d + 32]),
                                      sq[d + 64]), sq[d + 96]);
        #pragma unroll
        for (int o = 16; o; o >>= 1)
            a = __fadd_rn(a, __shfl_down_sync(0xffffffffu, a, o));
        if (d == 0) snrm = __fsqrt_rn(a);
    }
    __syncthreads();
    float nrm = fmaxf(snrm, 1e-8f);
    g_metanT[d * KPAD + i] = (i < KTOP) ? __fdiv_rn(meta, nrm) : 0.f;
}

// -------------------- K6: big GEMM + fused epilogue -------------------------
// Restructured for occupancy: no E smem tile (E streamed from global, block
// slice stays L2-resident across the 13 chunk re-reads); only the 32-row A
// chunk lives in smem (16KB) -> 4 CTAs/SM (16 warps). Per-output math is a
// bit-identical ascending-d serial FFMA chain, identical px<->thread map.
__device__ __forceinline__ void emit_row(int row, float xa, float xb,
                                         int pxb, int tid, int lane, int warp,
                                         int kp) {
    float m  = kp ? 1.f : 0.f;
    float v0 = __fmul_rn(m, xla_sigmoid(xa));
    float v1 = __fmul_rn(m, xla_sigmoid(xb));
    size_t base = (size_t)row * NPIX + pxb;
    g_pred[base + tid]       = v0;
    g_pred[base + 128 + tid] = v1;
    unsigned mm0 = __ballot_sync(0xffffffffu, v0 > 0.45f);
    unsigned mm1 = __ballot_sync(0xffffffffu, v1 > 0.45f);
    if (lane == 0) {
        g_bits[row * WORDS + (pxb >> 5) + warp]     = mm0;
        g_bits[row * WORDS + (pxb >> 5) + 4 + warp] = mm1;
    }
}

__global__ void __launch_bounds__(128, 4) k_gemm(const float* __restrict__ E) {
    __shared__ float sA[128 * 32];     // [d][r], 16 KB
    __shared__ int skeep[KTOP];
    int tid  = threadIdx.x;
    int pxb  = blockIdx.x * 256;
    int lane = tid & 31, warp = tid >> 5;

    for (int i = tid; i < KTOP; i += 128) skeep[i] = g_keep[i];

    #pragma unroll 1
    for (int chunk = 0; chunk < NCHUNK; ++chunk) {
        __syncthreads();
        for (int i = tid; i < 128 * 32; i += 128) {
            int d = i >> 5, r = i & 31;
            sA[d * 32 + r] = g_metanT[d * KPAD + chunk * 32 + r];
        }
        __syncthreads();

        unsigned long long a0[16], a1[16];
        #pragma unroll
        for (int r = 0; r < 16; r++) { a0[r] = 0ull; a1[r] = 0ull; }

        const float* pe = E + pxb + tid;   // px0 at [0], px1 at [128]
        #pragma unroll 4
        for (int d = 0; d < 128; d++) {
            float e0 = pe[0];
            float e1 = pe[128];
            pe += NPIX;
            unsigned eu0 = __float_as_uint(e0), eu1 = __float_as_uint(e1);
            unsigned long long e00, e11;
            asm("mov.b64 %0, {%1, %1};" : "=l"(e00) : "r"(eu0));
            asm("mov.b64 %0, {%1, %1};" : "=l"(e11) : "r"(eu1));
            const ulonglong2* ap = (const ulonglong2*)(sA + d * 32);
            #pragma unroll
            for (int q = 0; q < 8; q++) {
                ulonglong2 av = ap[q];        // rows (4q..4q+3), LDS.128 bcast
                ffma2(a0[2 * q],     av.x, e00);
                ffma2(a0[2 * q + 1], av.y, e00);
                ffma2(a1[2 * q],     av.x, e11);
                ffma2(a1[2 * q + 1], av.y, e11);
            }
        }

        int cb = chunk * 32;
        #pragma unroll
        for (int r = 0; r < 16; r++) {
            unsigned lo0, hi0, lo1, hi1;
            asm("mov.b64 {%0, %1}, %2;" : "=r"(lo0), "=r"(hi0) : "l"(a0[r]));
            asm("mov.b64 {%0, %1}, %2;" : "=r"(lo1), "=r"(hi1) : "l"(a1[r]));
            int row0 = cb + 2 * r;
            if (row0 < KTOP)
                emit_row(row0, __uint_as_float(lo0), __uint_as_float(lo1),
                         pxb, tid, lane, warp, skeep[row0]);
            int row1 = row0 + 1;
            if (row1 < KTOP)
                emit_row(row1, __uint_as_float(hi0), __uint_as_float(hi1),
                         pxb, tid, lane, warp, skeep[row1]);
        }
    }
}

// ---------------- K6b: XLA-GPU-order fp32 seg-sum emulation -----------------
__global__ void __launch_bounds__(1024) k_segsum() {   // <<<KTOP, 1024>>>
    __shared__ float wp[32];
    __shared__ int   wc[32];
    int row = blockIdx.x, t = threadIdx.x;
    int lane = t & 31, warp = t >> 5;
    const float2* p = (const float2*)&g_pred[(size_t)row * NPIX];
    float a0 = 0.f, a1 = 0.f;
    int c = 0;
    #pragma unroll 4
    for (int m2 = 0; m2 < NPIX / 2048; m2++) {   // 128 iters
        float2 v = p[t + 1024 * m2];
        if (v.x > 0.45f) { a0 = __fadd_rn(a0, v.x); c++; }
        if (v.y > 0.45f) { a1 = __fadd_rn(a1, v.y); c++; }
    }
    float a = __fadd_rn(a0, a1);
    #pragma unroll
    for (int o = 16; o; o >>= 1) {
        a = __fadd_rn(a, __shfl_down_sync(0xffffffffu, a, o));
        c += __shfl_down_sync(0xffffffffu, c, o);
    }
    if (lane == 0) { wp[warp] = a; wc[warp] = c; }
    __syncthreads();
    if (warp == 0) {
        float b = wp[lane];
        int   d = wc[lane];
        #pragma unroll
        for (int o = 16; o; o >>= 1) {
            b = __fadd_rn(b, __shfl_down_sync(0xffffffffu, b, o));
            d += __shfl_down_sync(0xffffffffu, d, o);
        }
        if (lane == 0) { g_segsum[row] = b; g_summask[row] = (float)d; }
    }
}

// -------------------- K7: cate scores + stable argsort ----------------------
__global__ void k_sort() {
    __shared__ unsigned long long key[512];
    int t = threadIdx.x;
    if (t < KTOP) {
        float seg  = __fdiv_rn(g_segsum[t], fmaxf(g_summask[t], 1.f));
        float cate = __fmul_rn(__fmul_rn(g_scores[t], seg),
                               g_keep[t] ? 1.f : 0.f);
        g_cate[t] = cate;
        float v = (cate > 0.f) ? -cate : 0.f;   // canonicalize zeros
        key[t] = (((unsigned long long)ford(v)) << 32) | (unsigned)t;
    } else key[t] = ~0ull;
    __syncthreads();
    for (int k = 2; k <= 512; k <<= 1)
        for (int j = k >> 1; j > 0; j >>= 1) {
            int i = t, ixj = i ^ j;
            if (ixj > i) {
                unsigned long long a = key[i], b = key[ixj];
                bool up = ((i & k) == 0);
                if ((a > b) == up) { key[i] = b; key[ixj] = a; }
            }
            __syncthreads();
        }
    if (t < KTOP) {
        int o = (int)(key[t] & 0xFFFFFFFFu);
        g_order[t]     = o;
        g_cate_s[t]    = g_cate[o];
        g_keeps[t]     = g_keep[o];
        g_summask_s[t] = g_summask[o];
    }
}

// -------------------- K8: bit-packed intersection SYRK ----------------------
__global__ void k_inter() {
    __shared__ unsigned sAb[32 * 33];
    __shared__ unsigned sBb[32 * 33];
    int t = threadIdx.x;                 // 256
    int b = blockIdx.x;                  // 0..90 triangular tile
    int ti = 0, rem = b;
    while (rem >= 13 - ti) { rem -= 13 - ti; ti++; }
    int tj = ti + rem;
    int wbase0 = blockIdx.y * 1024;
    int i0 = t >> 5;
    int jj = t & 31;
    int cnt[4] = {0, 0, 0, 0};
    for (int cc = 0; cc < 32; cc++) {
        int wb = wbase0 + cc * 32;
        for (int x = t; x < 1024; x += 256) {
            int r = x >> 5, c = x & 31;
            int ra = ti * 32 + r, rb = tj * 32 + r;
            sAb[c * 33 + r] = (ra < KTOP) ? g_bits[ra * WORDS + wb + c] : 0u;
            sBb[c * 33 + r] = (rb < KTOP) ? g_bits[rb * WORDS + wb + c] : 0u;
        }
        __syncthreads();
        #pragma unroll 4
        for (int w = 0; w < 32; w++) {
            unsigned bv = sBb[w * 33 + jj];
            #pragma unroll
            for (int k2 = 0; k2 < 4; k2++) {
                unsigned av = sAb[w * 33 + i0 + 8 * k2];
                cnt[k2] += __popc(av & bv);
            }
        }
        __syncthreads();
    }
    #pragma unroll
    for (int k2 = 0; k2 < 4; k2++) {
        int ii = ti * 32 + i0 + 8 * k2;
        int j2 = tj * 32 + jj;
        if (ii < KTOP && j2 < KTOP) {
            atomicAdd(&g_inter[ii * KTOP + j2], cnt[k2]);
            if (ti != tj) atomicAdd(&g_inter[j2 * KTOP + ii], cnt[k2]);
        }
    }
}

// -------------------- K9: sorted IoU + column max ---------------------------
__global__ void k_iou1() {
    __shared__ float sms[KTOP];
    __shared__ int   ords[KTOP];
    int t = threadIdx.x;                  // 512
    if (t < KTOP) { sms[t] = g_summask_s[t]; ords[t] = g_order[t]; }
    __syncthreads();
    if (t >= KTOP) return;
    int j = t, b2 = ords[j];
    float smj = sms[j], comp = 0.f;
    for (int i = 0; i < j; i++) {
        float it  = (float)g_inter[ords[i] * KTOP + b2];
        float den = __fadd_rn(__fadd_rn(sms[i], smj), -it);
        float iou = (den > 0.f) ? __fdiv_rn(it, fmaxf(den, 1.f)) : 0.f;
        g_iou[i * KTOP + j] = iou;
        comp = fmaxf(comp, iou);
    }
    g_comp[j] = comp;
}

// -------------------- K10: matrix-NMS decay + small outputs -----------------
__global__ void k_nms2(float* __restrict__ out) {
    __shared__ float den[KTOP];
    int t = threadIdx.x;                  // 512
    if (t < KTOP) {
        float c  = g_comp[t];
        float c2 = __fmul_rn(c, c);       // exp(-SIGMA * x**2) association
        den[t] = expf(__fmul_rn(-2.f, c2));
    }
    __syncthreads();
    if (t >= KTOP) return;
    int j = t;
    float dmin = 3.4e38f;
    for (int i = 0; i < KTOP; i++) {
        float d  = (i < j) ? g_iou[i * KTOP + j] : 0.f;
        float d2 = __fmul_rn(d, d);
        float term = __fdiv_rn(expf(__fmul_rn(-2.f, d2)), den[i]);
        dmin = fminf(dmin, term);
    }
    float fs = __fmul_rn(g_cate_s[j], dmin);
    out[j]            = fs;
    out[OUT_KEEP + j] = (fs >= 0.8f && g_keeps[j]) ? 1.f : 0.f;
    out[OUT_IDX + j]  = (float)g_index[g_order[j]];
}

// -------------------- K11: permuted float4 mask copy ------------------------
__global__ void k_copy(float* __restrict__ out) {
    int i   = blockIdx.y;
    int src = g_order[i];
    int f4  = blockIdx.x * 256 + threadIdx.x;
    const float4* s = (const float4*)&g_pred[(size_t)src * NPIX];
    float4* d       = (float4*)(out + OUT_MASK + (size_t)i * NPIX);
    d[f4] = s[f4];
}

// ---------------------------------------------------------------------------
extern "C" void kernel_launch(void* const* d_in, const int* in_sizes, int n_in,
                              void* d_out, int out_size) {
    const float* logits = (const float*)d_in[0];
    const float* em     = (const float*)d_in[1];
    const float* E      = (const float*)d_in[2];
    float* out = (float*)d_out;

    k_init<<<625, 256>>>();
    k_topk<<<1, 1024>>>(logits);
    k_feat<<<KTOP, DIM>>>(em);
    k_sim<<<KTOP, DIM>>>();
    k_firstkeep<<<1, 512>>>();
    k_meta<<<KPAD, DIM>>>();
    k_gemm<<<NBLK, 128>>>(E);
    k_segsum<<<KTOP, 1024>>>();
    k_sort<<<1, 512>>>();
    k_inter<<<dim3(91, 8), 256>>>();
    k_iou1<<<1, 512>>>();
    k_nms2<<<1, 512>>>(out);
    k_copy<<<dim3(256, 400), 256>>>(out);
}

// round 16
// speedup vs baseline: 1.5036x; 1.0504x over previous
#include <cuda_runtime.h>
#include <math.h>

// ---------------------------------------------------------------------------
// SparseInst post-processing pipeline, fixed shapes:
//   pred_logits     [1,1,128,128]   -> 16384 fp32
//   embedding_masks [1,128,128,128] -> [128][16384]
//   encode_feat     [1,128,512,512] -> [128][262144]
//   K = 400
// Outputs: final_scores[400], pred_masks_s[400*262144], keep_final[400],
//          center_index[400]
//
// Numerical contract (validated PASS, rounds 11/14):
//  * matmuls: exact fp32, ascending-k serial FMA chain per output.
//  * sigmoid: XLA logistic_expander 0.5 + 0.5*tanh(0.5x), XLA FastTanh f32.
//  * seg row-sum: XLA-GPU tree order (k_segsum).
// This round: cache-policy hints only (__stcs/__ldcs), deeper unroll for
// MLP, and launch reorder so ncu (-s 5) profiles k_gemm. No math changes.
// ---------------------------------------------------------------------------

#define KTOP   400
#define DIM    128
#define HW     16384
#define NPIX   262144
#define WORDS  8192          // NPIX/32
#define KPAD   416           // 13*32
#define NCHUNK 13
#define NBLK   1024          // gemm blocks
#define OUT_MASK 400
#define OUT_KEEP 104858000   // 400 + 400*262144
#define OUT_IDX  104858400

// ------------------------------ scratch ------------------------------------
__device__ float         g_scores[KTOP];
__device__ int           g_index[KTOP];
__device__ int           g_valid[KTOP];
__device__ float         g_feat[KTOP * DIM];
__device__ float         g_fn[KTOP * DIM];
__device__ float         g_sim[KTOP * KTOP];
__device__ int           g_first[KTOP];
__device__ int           g_keep[KTOP];
__device__ float         g_metanT[DIM * KPAD];         // [d][row]
__device__ float         g_pred[(size_t)KTOP * NPIX];  // unsorted masks (419MB)
__device__ unsigned int  g_bits[KTOP * WORDS];         // segf bitmask
__device__ float         g_segsum[KTOP];
__device__ float         g_summask[KTOP];
__device__ float         g_cate[KTOP];
__device__ float         g_cate_s[KTOP];
__device__ int           g_keeps[KTOP];
__device__ float         g_summask_s[KTOP];
__device__ int           g_order[KTOP];
__device__ int           g_inter[KTOP * KTOP];
__device__ float         g_iou[KTOP * KTOP];
__device__ float         g_comp[KTOP];

// ------------------------------ helpers ------------------------------------
__device__ __forceinline__ unsigned ford(float f) {
    unsigned u = __float_as_uint(f);
    return (u & 0x80000000u) ? ~u : (u | 0x80000000u);
}

// XLA FastTanh (f32): |x|<0.0004 -> x; clamp +-7.90531110763549805;
// odd rational with the exact XLA alpha/beta coefficients, FMA chains.
__device__ __forceinline__ float xla_tanh(float x) {
    if (fabsf(x) < 0.0004f) return x;
    float xc = fminf(fmaxf(x, -7.90531110763549805f), 7.90531110763549805f);
    float x2 = __fmul_rn(xc, xc);
    float p = __fmaf_rn(x2, -2.76076847742355e-16f, 2.00018790482477e-13f);
    p = __fmaf_rn(x2, p, -8.60467152213735e-11f);
    p = __fmaf_rn(x2, p,  5.12229709037114e-08f);
    p = __fmaf_rn(x2, p,  1.48572235717979e-05f);
    p = __fmaf_rn(x2, p,  6.37261928875436e-04f);
    p = __fmaf_rn(x2, p,  4.89352455891786e-03f);
    p = __fmul_rn(p, xc);
    float q = __fmaf_rn(x2, 1.19825839466702e-06f, 1.18534705686654e-04f);
    q = __fmaf_rn(x2, q, 2.26843463243900e-03f);
    q = __fmaf_rn(x2, q, 4.89352518554385e-03f);
    return __fdiv_rn(p, q);
}

// XLA logistic expansion: 0.5 + 0.5*tanh(0.5*x), ops rounded individually
__device__ __forceinline__ float xla_sigmoid(float x) {
    float t = xla_tanh(__fmul_rn(0.5f, x));
    return __fadd_rn(0.5f, __fmul_rn(0.5f, t));
}

__device__ __forceinline__ void ffma2(unsigned long long &acc,
                                      unsigned long long a,
                                      unsigned long long b) {
    asm("fma.rn.f32x2 %0, %1, %2, %0;" : "+l"(acc) : "l"(a), "l"(b));
}

// ------------------------------ K0: init -----------------------------------
__global__ void k_init() {
    int i = blockIdx.x * 256 + threadIdx.x;
    if (i < KTOP * KTOP) g_inter[i] = 0;
}

// ------------------ K1: sigmoid + exact stable top-400 ----------------------
__global__ void k_topk(const float* __restrict__ logits) {
    __shared__ unsigned long long cand[4096];   // aliased as hist in phase 1
    __shared__ int s_cnt, s_bin;
    int* hist = (int*)cand;
    int tid = threadIdx.x;
    for (int i = tid; i < 4096; i += 1024) hist[i] = 0;
    if (tid == 0) s_cnt = 0;
    __syncthreads();
    for (int i = tid; i < HW; i += 1024) {
        float p = xla_sigmoid(logits[i]);
        unsigned d = ~ford(p);                 // ascending d == descending p
        atomicAdd(&hist[d >> 19], 1);          // d < 2^31 -> bin < 4096
    }
    __syncthreads();
    if (tid == 0) {
        int c = 0, b = 0;
        for (; b < 4096; b++) { c += hist[b]; if (c >= KTOP) break; }
        s_bin = b;
    }
    __syncthreads();
    int bt = s_bin;
    for (int i = tid; i < 4096; i += 1024) cand[i] = ~0ull;  // clear (aliases hist)
    __syncthreads();
    for (int i = tid; i < HW; i += 1024) {
        float p = xla_sigmoid(logits[i]);
        unsigned d = ~ford(p);
        if ((int)(d >> 19) <= bt) {
            int pos = atomicAdd(&s_cnt, 1);
            if (pos < 4096)
                cand[pos] = (((unsigned long long)d) << 32) | (unsigned)i;
        }
    }
    __syncthreads();
    // bitonic sort ascending: (desc value, asc index) == lax.top_k order
    for (int k = 2; k <= 4096; k <<= 1)
        for (int j = k >> 1; j > 0; j >>= 1) {
            for (int i = tid; i < 4096; i += 1024) {
                int ixj = i ^ j;
                if (ixj > i) {
                    unsigned long long a = cand[i], b2 = cand[ixj];
                    bool up = ((i & k) == 0);
                    if ((a > b2) == up) { cand[i] = b2; cand[ixj] = a; }
                }
            }
            __syncthreads();
        }
    if (tid < KTOP) {
        unsigned long long kk = cand[tid];
        unsigned fo = ~((unsigned)(kk >> 32));
        float p = __uint_as_float(fo & 0x7FFFFFFFu);   // p in [0,1)
        g_scores[tid] = p;
        g_index[tid]  = (int)(kk & 0xFFFFFFFFu);
        g_valid[tid]  = (p > 0.75f) ? 1 : 0;
    }
}

// -------------------- K2: gather feat + normalize ---------------------------
__global__ void k_feat(const float* __restrict__ em) {
    int i = blockIdx.x, d = threadIdx.x;
    __shared__ float sq[DIM];
    __shared__ float snrm;
    int idx = g_index[i];
    float f = em[d * HW + idx];
    sq[d] = f * f;
    __syncthreads();
    if (d < 32) {
        float a = __fadd_rn(__fadd_rn(__fadd_rn(sq[d], sq[d + 32]),
                                      sq[d + 64]), sq[d + 96]);
        #pragma unroll
        for (int o = 16; o; o >>= 1)
            a = __fadd_rn(a, __shfl_down_sync(0xffffffffu, a, o));
        if (d == 0) snrm = __fsqrt_rn(a);
    }
    __syncthreads();
    float nrm = fmaxf(snrm, 1e-8f);
    g_feat[i * DIM + d] = f;
    g_fn[i * DIM + d]   = __fdiv_rn(f, nrm);
}

// -------------------- K3: sim = fn @ fn.T (upper triangle) ------------------
__global__ void k_sim() {
    int i = blockIdx.x, t = threadIdx.x;
    __shared__ float fi[DIM];
    fi[t] = g_fn[i * DIM + t];
    __syncthreads();
    for (int jj = i + t; jj < KTOP; jj += DIM) {   // only j >= i is ever read
        const float4* fj = (const float4*)&g_fn[jj * DIM];
        float s = 0.f;
        #pragma unroll
        for (int d4 = 0; d4 < 32; d4++) {
            float4 v = fj[d4];
            int k = d4 * 4;
            s = __fmaf_rn(fi[k],     v.x, s);
            s = __fmaf_rn(fi[k + 1], v.y, s);
            s = __fmaf_rn(fi[k + 2], v.z, s);
            s = __fmaf_rn(fi[k + 3], v.w, s);
        }
        g_sim[i * KTOP + jj] = s;
    }
}

// -------------------- K4: first-label column + keep -------------------------
__global__ void k_firstkeep() {
    int j = threadIdx.x;
    if (j >= KTOP) return;
    int first = -1;
    if (g_valid[j]) {
        for (int i = 0; i <= j; i++) {
            if (g_valid[i] && g_sim[i * KTOP + j] >= 0.85f) { first = i; break; }
        }
    }
    g_first[j] = first;
    g_keep[j]  = (g_valid[j] && first == j) ? 1 : 0;
}

// -------------------- K5: meta fusion + normalize -> metanT -----------------
__global__ void k_meta() {
    int i = blockIdx.x, d = threadIdx.x;
    __shared__ float sq[DIM];
    __shared__ float snrm;
    float meta = 0.f;
    if (i < KTOP) {
        float s = 0.f; int cnt = 0;
        for (int j = 0; j < KTOP; j++) {          // ascending j == dot order
            if (g_first[j] == i) { s = __fadd_rn(s, g_feat[j * DIM + d]); cnt++; }
        }
        meta = g_keep[i] ? __fdiv_rn(s, fmaxf((float)cnt, 1.f)) : 0.f;
    }
    sq[d] = meta * meta;
    __syncthreads();
    if (d < 32) {
        float a = __fadd_rn(__fadd_rn(__fadd_rn(sq[d], sq[d + 32]),
                                      sq[d + 64]), sq[d + 96]);
        #pragma unroll
        for (int o = 16; o; o >>= 1)
            a = __fadd_rn(a, __shfl_down_sync(0xffffffffu, a, o));
        if (d == 0) snrm = __fsqrt_rn(a);
    }
    __syncthreads();
    float nrm = fmaxf(snrm, 1e-8f);
    g_metanT[d * KPAD + i] = (i < KTOP) ? __fdiv_rn(meta, nrm) : 0.f;
}

// -------------------- K6: big GEMM + fused epilogue -------------------------
// E streamed from global (block slice L2-resident across 13 chunk re-reads;
// g_pred written with evict-first .cs so the 419MB stream does not evict E).
// Per-output math: bit-identical ascending-d serial FFMA chain.
__device__ __forceinline__ void emit_row(int row, float xa, float xb,
                                         int pxb, int tid, int lane, int warp,
                                         int kp) {
    float m  = kp ? 1.f : 0.f;
    float v0 = __fmul_rn(m, xla_sigmoid(xa));
    float v1 = __fmul_rn(m, xla_sigmoid(xb));
    size_t base = (size_t)row * NPIX + pxb;
    __stcs(&g_pred[base + tid], v0);
    __stcs(&g_pred[base + 128 + tid], v1);
    unsigned mm0 = __ballot_sync(0xffffffffu, v0 > 0.45f);
    unsigned mm1 = __ballot_sync(0xffffffffu, v1 > 0.45f);
    if (lane == 0) {
        g_bits[row * WORDS + (pxb >> 5) + warp]     = mm0;
        g_bits[row * WORDS + (pxb >> 5) + 4 + warp] = mm1;
    }
}

__global__ void __launch_bounds__(128, 4) k_gemm(const float* __restrict__ E) {
    __shared__ float sA[128 * 32];     // [d][r], 16 KB
    __shared__ int skeep[KTOP];
    int tid  = threadIdx.x;
    int pxb  = blockIdx.x * 256;
    int lane = tid & 31, warp = tid >> 5;

    for (int i = tid; i < KTOP; i += 128) skeep[i] = g_keep[i];

    #pragma unroll 1
    for (int chunk = 0; chunk < NCHUNK; ++chunk) {
        __syncthreads();
        for (int i = tid; i < 128 * 32; i += 128) {
            int d = i >> 5, r = i & 31;
            sA[d * 32 + r] = g_metanT[d * KPAD + chunk * 32 + r];
        }
        __syncthreads();

        unsigned long long a0[16], a1[16];
        #pragma unroll
        for (int r = 0; r < 16; r++) { a0[r] = 0ull; a1[r] = 0ull; }

        const float* pe = E + pxb + tid;   // px0 at [0], px1 at [128]
        #pragma unroll 8
        for (int d = 0; d < 128; d++) {
            float e0 = pe[0];
            float e1 = pe[128];
            pe += NPIX;
            unsigned eu0 = __float_as_uint(e0), eu1 = __float_as_uint(e1);
            unsigned long long e00, e11;
            asm("mov.b64 %0, {%1, %1};" : "=l"(e00) : "r"(eu0));
            asm("mov.b64 %0, {%1, %1};" : "=l"(e11) : "r"(eu1));
            const ulonglong2* ap = (const ulonglong2*)(sA + d * 32);
            #pragma unroll
            for (int q = 0; q < 8; q++) {
                ulonglong2 av = ap[q];        // rows (4q..4q+3), LDS.128 bcast
                ffma2(a0[2 * q],     av.x, e00);
                ffma2(a0[2 * q + 1], av.y, e00);
                ffma2(a1[2 * q],     av.x, e11);
                ffma2(a1[2 * q + 1], av.y, e11);
            }
        }

        int cb = chunk * 32;
        #pragma unroll
        for (int r = 0; r < 16; r++) {
            unsigned lo0, hi0, lo1, hi1;
            asm("mov.b64 {%0, %1}, %2;" : "=r"(lo0), "=r"(hi0) : "l"(a0[r]));
            asm("mov.b64 {%0, %1}, %2;" : "=r"(lo1), "=r"(hi1) : "l"(a1[r]));
            int row0 = cb + 2 * r;
            if (row0 < KTOP)
                emit_row(row0, __uint_as_float(lo0), __uint_as_float(lo1),
                         pxb, tid, lane, warp, skeep[row0]);
            int row1 = row0 + 1;
            if (row1 < KTOP)
                emit_row(row1, __uint_as_float(hi0), __uint_as_float(hi1),
                         pxb, tid, lane, warp, skeep[row1]);
        }
    }
}

// ---------------- K6b: XLA-GPU-order fp32 seg-sum emulation -----------------
__global__ void __launch_bounds__(1024) k_segsum() {   // <<<KTOP, 1024>>>
    __shared__ float wp[32];
    __shared__ int   wc[32];
    int row = blockIdx.x, t = threadIdx.x;
    int lane = t & 31, warp = t >> 5;
    const float2* p = (const float2*)&g_pred[(size_t)row * NPIX];
    float a0 = 0.f, a1 = 0.f;
    int c = 0;
    #pragma unroll 4
    for (int m2 = 0; m2 < NPIX / 2048; m2++) {   // 128 iters
        float2 v = __ldcs(&p[t + 1024 * m2]);
        if (v.x > 0.45f) { a0 = __fadd_rn(a0, v.x); c++; }
        if (v.y > 0.45f) { a1 = __fadd_rn(a1, v.y); c++; }
    }
    float a = __fadd_rn(a0, a1);
    #pragma unroll
    for (int o = 16; o; o >>= 1) {
        a = __fadd_rn(a, __shfl_down_sync(0xffffffffu, a, o));
        c += __shfl_down_sync(0xffffffffu, c, o);
    }
    if (lane == 0) { wp[warp] = a; wc[warp] = c; }
    __syncthreads();
    if (warp == 0) {
        float b = wp[lane];
        int   d = wc[lane];
        #pragma unroll
        for (int o = 16; o; o >>= 1) {
            b = __fadd_rn(b, __shfl_down_sync(0xffffffffu, b, o));
            d += __shfl_down_sync(0xffffffffu, d, o);
        }
        if (lane == 0) { g_segsum[row] = b; g_summask[row] = (float)d; }
    }
}

// -------------------- K7: cate scores + stable argsort ----------------------
__global__ void k_sort() {
    __shared__ unsigned long long key[512];
    int t = threadIdx.x;
    if (t < KTOP) {
        float seg  = __fdiv_rn(g_segsum[t], fmaxf(g_summask[t], 1.f));
        float cate = __fmul_rn(__fmul_rn(g_scores[t], seg),
                               g_keep[t] ? 1.f : 0.f);
        g_cate[t] = cate;
        float v = (cate > 0.f) ? -cate : 0.f;   // canonicalize zeros
        key[t] = (((unsigned long long)ford(v)) << 32) | (unsigned)t;
    } else key[t] = ~0ull;
    __syncthreads();
    for (int k = 2; k <= 512; k <<= 1)
        for (int j = k >> 1; j > 0; j >>= 1) {
            int i = t, ixj = i ^ j;
            if (ixj > i) {
                unsigned long long a = key[i], b = key[ixj];
                bool up = ((i & k) == 0);
                if ((a > b) == up) { key[i] = b; key[ixj] = a; }
            }
            __syncthreads();
        }
    if (t < KTOP) {
        int o = (int)(key[t] & 0xFFFFFFFFu);
        g_order[t]     = o;
        g_cate_s[t]    = g_cate[o];
        g_keeps[t]     = g_keep[o];
        g_summask_s[t] = g_summask[o];
    }
}

// -------------------- K8: bit-packed intersection SYRK ----------------------
__global__ void k_inter() {
    __shared__ unsigned sAb[32 * 33];
    __shared__ unsigned sBb[32 * 33];
    int t = threadIdx.x;                 // 256
    int b = blockIdx.x;                  // 0..90 triangular tile
    int ti = 0, rem = b;
    while (rem >= 13 - ti) { rem -= 13 - ti; ti++; }
    int tj = ti + rem;
    int wbase0 = blockIdx.y * 1024;
    int i0 = t >> 5;
    int jj = t & 31;
    int cnt[4] = {0, 0, 0, 0};
    for (int cc = 0; cc < 32; cc++) {
        int wb = wbase0 + cc * 32;
        for (int x = t; x < 1024; x += 256) {
            int r = x >> 5, c = x & 31;
            int ra = ti * 32 + r, rb = tj * 32 + r;
            sAb[c * 33 + r] = (ra < KTOP) ? g_bits[ra * WORDS + wb + c] : 0u;
            sBb[c * 33 + r] = (rb < KTOP) ? g_bits[rb * WORDS + wb + c] : 0u;
        }
        __syncthreads();
        #pragma unroll 4
        for (int w = 0; w < 32; w++) {
            unsigned bv = sBb[w * 33 + jj];
            #pragma unroll
            for (int k2 = 0; k2 < 4; k2++) {
                unsigned av = sAb[w * 33 + i0 + 8 * k2];
                cnt[k2] += __popc(av & bv);
            }
        }
        __syncthreads();
    }
    #pragma unroll
    for (int k2 = 0; k2 < 4; k2++) {
        int ii = ti * 32 + i0 + 8 * k2;
        int j2 = tj * 32 + jj;
        if (ii < KTOP && j2 < KTOP) {
            atomicAdd(&g_inter[ii * KTOP + j2], cnt[k2]);
            if (ti != tj) atomicAdd(&g_inter[j2 * KTOP + ii], cnt[k2]);
        }
    }
}

// -------------------- K9: sorted IoU + column max ---------------------------
__global__ void k_iou1() {
    __shared__ float sms[KTOP];
    __shared__ int   ords[KTOP];
    int t = threadIdx.x;                  // 512
    if (t < KTOP) { sms[t] = g_summask_s[t]; ords[t] = g_order[t]; }
    __syncthreads();
    if (t >= KTOP) return;
    int j = t, b2 = ords[j];
    float smj = sms[j], comp = 0.f;
    for (int i = 0; i < j; i++) {
        float it  = (float)g_inter[ords[i] * KTOP + b2];
        float den = __fadd_rn(__fadd_rn(sms[i], smj), -it);
        float iou = (den > 0.f) ? __fdiv_rn(it, fmaxf(den, 1.f)) : 0.f;
        g_iou[i * KTOP + j] = iou;
        comp = fmaxf(comp, iou);
    }
    g_comp[j] = comp;
}

// -------------------- K10: matrix-NMS decay + small outputs -----------------
__global__ void k_nms2(float* __restrict__ out) {
    __shared__ float den[KTOP];
    int t = threadIdx.x;                  // 512
    if (t < KTOP) {
        float c  = g_comp[t];
        float c2 = __fmul_rn(c, c);       // exp(-SIGMA * x**2) association
        den[t] = expf(__fmul_rn(-2.f, c2));
    }
    __syncthreads();
    if (t >= KTOP) return;
    int j = t;
    float dmin = 3.4e38f;
    for (int i = 0; i < KTOP; i++) {
        float d  = (i < j) ? g_iou[i * KTOP + j] : 0.f;
        float d2 = __fmul_rn(d, d);
        float term = __fdiv_rn(expf(__fmul_rn(-2.f, d2)), den[i]);
        dmin = fminf(dmin, term);
    }
    float fs = __fmul_rn(g_cate_s[j], dmin);
    out[j]            = fs;
    out[OUT_KEEP + j] = (fs >= 0.8f && g_keeps[j]) ? 1.f : 0.f;
    out[OUT_IDX + j]  = (float)g_index[g_order[j]];
}

// -------------------- K11: permuted float4 mask copy ------------------------
__global__ void k_copy(float* __restrict__ out) {
    int i   = blockIdx.y;
    int src = g_order[i];
    int f4  = blockIdx.x * 256 + threadIdx.x;
    const float4* s = (const float4*)&g_pred[(size_t)src * NPIX];
    float4* d       = (float4*)(out + OUT_MASK + (size_t)i * NPIX);
    float4 v = __ldcs(&s[f4]);
    __stcs(&d[f4], v);
}

// ---------------------------------------------------------------------------
extern "C" void kernel_launch(void* const* d_in, const int* in_sizes, int n_in,
                              void* d_out, int out_size) {
    const float* logits = (const float*)d_in[0];
    const float* em     = (const float*)d_in[1];
    const float* E      = (const float*)d_in[2];
    float* out = (float*)d_out;

    // launch order chosen so k_gemm is launch #6 (ncu -s 5 -c 1 profiles it)
    k_topk<<<1, 1024>>>(logits);
    k_feat<<<KTOP, DIM>>>(em);
    k_sim<<<KTOP, DIM>>>();
    k_firstkeep<<<1, 512>>>();
    k_meta<<<KPAD, DIM>>>();
    k_gemm<<<NBLK, 128>>>(E);
    k_segsum<<<KTOP, 1024>>>();
    k_init<<<625, 256>>>();          // zero g_inter (needed before k_inter)
    k_sort<<<1, 512>>>();
    k_inter<<<dim3(91, 8), 256>>>();
    k_iou1<<<1, 512>>>();
    k_nms2<<<1, 512>>>(out);
    k_copy<<<dim3(256, 400), 256>>>(out);
}